// round 1
// baseline (speedup 1.0000x reference)
#include <cuda_runtime.h>

// ---------------------------------------------------------------------------
// DeformableAttention (B=8, N=4096, C=256, S=4, NH=8, NL=1, NP=4, HD=32)
//
// Pipeline (all fp32):
//   1. vmean   = mean_s v                       (4096 x 256)
//   2. Woffc   = Wq @ Woff     (256x64)   ; Wattnc = Wq @ Wattn (256x32)
//      boffc   = bq @ Woff + boff ; battnc = bq @ Wattn + battn
//   3. vpm     = vmean @ Wv + bv                (4096 x 256)
//   4. off     = q @ Woffc + boffc              (32768 x 64)
//      attn    = q @ Wattnc + battnc            (32768 x 32)
//   5. sampling: softmax over 4 pts/head, bilinear gather from vpm,
//      weighted sum -> pre (32768 x 256)
//   6. out     = pre @ Wo + bo                  (32768 x 256)
// ---------------------------------------------------------------------------

namespace {
constexpr int Bn   = 8;
constexpr int Nn   = 4096;
constexpr int Cc   = 256;
constexpr int NHh  = 8;
constexpr int NPp  = 4;
constexpr int HDd  = 32;
constexpr int ROWS = Bn * Nn;    // 32768
constexpr int GW   = 64;         // grid width/height (sqrt(N))
}

// -------------------- scratch (static device globals; no allocs) -----------
__device__ __align__(16) float g_vmean[Nn * Cc];
__device__ __align__(16) float g_vpm[Nn * Cc];
__device__ __align__(16) float g_Woffc[Cc * 64];
__device__ __align__(16) float g_Wattnc[Cc * 32];
__device__ __align__(16) float g_boffc[64];
__device__ __align__(16) float g_battnc[32];
__device__ __align__(16) float g_off[(size_t)ROWS * 64];
__device__ __align__(16) float g_attn[(size_t)ROWS * 32];
__device__ __align__(16) float g_pre[(size_t)ROWS * Cc];

// -------------------- generic tiled SGEMM: C = A(MxK) @ B(KxN) + bias ------
template <int BM, int BN, int BK, int TM, int TN>
__global__ void __launch_bounds__((BM / TM) * (BN / TN))
sgemm_bias_kernel(const float* __restrict__ A, const float* __restrict__ Bm,
                  const float* __restrict__ bias, float* __restrict__ C,
                  int M, int N, int K) {
    static_assert(TN == 4, "output store assumes TN==4");
    constexpr int THREADS = (BM / TM) * (BN / TN);
    __shared__ float As[BK][BM + 4];   // +4 pad: keeps 16B alignment, cuts bank conflicts
    __shared__ float Bs[BK][BN];

    const int tid = threadIdx.y * blockDim.x + threadIdx.x;
    const int block_row = blockIdx.y * BM;
    const int block_col = blockIdx.x * BN;
    const int trow = threadIdx.y * TM;
    const int tcol = threadIdx.x * TN;

    constexpr int A_LD4 = BM * BK / 4 / THREADS;
    constexpr int B_LD4 = BK * BN / 4 / THREADS;

    float acc[TM][TN];
#pragma unroll
    for (int i = 0; i < TM; i++)
#pragma unroll
        for (int j = 0; j < TN; j++) acc[i][j] = 0.f;

    for (int k0 = 0; k0 < K; k0 += BK) {
#pragma unroll
        for (int l = 0; l < A_LD4; l++) {
            int idx = tid + l * THREADS;
            int r  = idx / (BK / 4);
            int c4 = (idx % (BK / 4)) * 4;
            float4 a = *reinterpret_cast<const float4*>(
                A + (size_t)(block_row + r) * K + k0 + c4);
            As[c4 + 0][r] = a.x;
            As[c4 + 1][r] = a.y;
            As[c4 + 2][r] = a.z;
            As[c4 + 3][r] = a.w;
        }
#pragma unroll
        for (int l = 0; l < B_LD4; l++) {
            int idx = tid + l * THREADS;
            int r  = idx / (BN / 4);
            int c4 = (idx % (BN / 4)) * 4;
            *reinterpret_cast<float4*>(&Bs[r][c4]) =
                *reinterpret_cast<const float4*>(Bm + (size_t)(k0 + r) * N + block_col + c4);
        }
        __syncthreads();
#pragma unroll
        for (int k = 0; k < BK; k++) {
            float a_frag[TM];
            float b_frag[TN];
#pragma unroll
            for (int i = 0; i < TM; i += 4) {
                float4 t = *reinterpret_cast<const float4*>(&As[k][trow + i]);
                a_frag[i] = t.x; a_frag[i + 1] = t.y;
                a_frag[i + 2] = t.z; a_frag[i + 3] = t.w;
            }
#pragma unroll
            for (int j = 0; j < TN; j += 4) {
                float4 t = *reinterpret_cast<const float4*>(&Bs[k][tcol + j]);
                b_frag[j] = t.x; b_frag[j + 1] = t.y;
                b_frag[j + 2] = t.z; b_frag[j + 3] = t.w;
            }
#pragma unroll
            for (int i = 0; i < TM; i++)
#pragma unroll
                for (int j = 0; j < TN; j++)
                    acc[i][j] = fmaf(a_frag[i], b_frag[j], acc[i][j]);
        }
        __syncthreads();
    }

    float bfrag[TN];
#pragma unroll
    for (int j = 0; j < TN; j++)
        bfrag[j] = bias ? bias[block_col + tcol + j] : 0.f;
#pragma unroll
    for (int i = 0; i < TM; i++) {
        float4 o;
        o.x = acc[i][0] + bfrag[0];
        o.y = acc[i][1] + bfrag[1];
        o.z = acc[i][2] + bfrag[2];
        o.w = acc[i][3] + bfrag[3];
        *reinterpret_cast<float4*>(
            C + (size_t)(block_row + trow + i) * N + block_col + tcol) = o;
    }
}

// -------------------- mean over S=4 source levels --------------------------
__global__ void vmean_kernel(const float* __restrict__ v) {
    const int tot = Nn * Cc / 4;
    int i = blockIdx.x * blockDim.x + threadIdx.x;
    if (i < tot) {
        const float4* v4 = reinterpret_cast<const float4*>(v);
        float4 a = v4[i], b = v4[i + tot], c = v4[i + 2 * tot], d = v4[i + 3 * tot];
        float4 r;
        r.x = 0.25f * (a.x + b.x + c.x + d.x);
        r.y = 0.25f * (a.y + b.y + c.y + d.y);
        r.z = 0.25f * (a.z + b.z + c.z + d.z);
        r.w = 0.25f * (a.w + b.w + c.w + d.w);
        reinterpret_cast<float4*>(g_vmean)[i] = r;
    }
}

// -------------------- combined biases: boffc = bq@Woff + boff; etc ---------
__global__ void biascomb_kernel(const float* __restrict__ bq,
                                const float* __restrict__ Woff,
                                const float* __restrict__ boff,
                                const float* __restrict__ Wattn,
                                const float* __restrict__ battn) {
    int j = threadIdx.x;
    if (j < 64) {
        float s = boff[j];
        for (int k = 0; k < Cc; k++) s += bq[k] * Woff[k * 64 + j];
        g_boffc[j] = s;
    } else if (j < 96) {
        int jj = j - 64;
        float s = battn[jj];
        for (int k = 0; k < Cc; k++) s += bq[k] * Wattn[k * 32 + jj];
        g_battnc[jj] = s;
    }
}

// -------------------- sampling: softmax + bilinear gather + weight ---------
// One warp per (b, n) row; lane = head-dim index (HD=32).
__global__ void __launch_bounds__(256) sample_kernel() {
    __shared__ float s_off[8][64];
    __shared__ float s_attn[8][32];
    const int w    = threadIdx.x >> 5;
    const int lane = threadIdx.x & 31;
    const int row  = blockIdx.x * 8 + w;

    const float* offrow = g_off + (size_t)row * 64;
    s_off[w][lane]      = offrow[lane];
    s_off[w][lane + 32] = offrow[lane + 32];
    s_attn[w][lane]     = g_attn[(size_t)row * 32 + lane];
    __syncwarp();

    const int n = row & (Nn - 1);
    const float refx = (float)(n & (GW - 1)) * (1.0f / 63.0f);
    const float refy = (float)(n >> 6) * (1.0f / 63.0f);
    float* outrow = g_pre + (size_t)row * Cc;

#pragma unroll
    for (int h = 0; h < NHh; h++) {
        // softmax over the 4 sampling points of this head (warp-uniform)
        float l0 = s_attn[w][h * 4 + 0];
        float l1 = s_attn[w][h * 4 + 1];
        float l2 = s_attn[w][h * 4 + 2];
        float l3 = s_attn[w][h * 4 + 3];
        float m  = fmaxf(fmaxf(l0, l1), fmaxf(l2, l3));
        float e0 = __expf(l0 - m), e1 = __expf(l1 - m);
        float e2 = __expf(l2 - m), e3 = __expf(l3 - m);
        float inv = 1.0f / (e0 + e1 + e2 + e3);
        float wp[4] = {e0 * inv, e1 * inv, e2 * inv, e3 * inv};

        const float* fmap = g_vpm + h * HDd + lane;  // column for this (head, dim)
        float acc = 0.f;
#pragma unroll
        for (int p = 0; p < NPp; p++) {
            float ox = s_off[w][h * 8 + p * 2 + 0];
            float oy = s_off[w][h * 8 + p * 2 + 1];
            float lx = fminf(fmaxf(refx + ox, 0.f), 1.f);
            float ly = fminf(fmaxf(refy + oy, 0.f), 1.f);
            // grid_sample align_corners=False: pixel coord = loc*size - 0.5
            float x = lx * (float)GW - 0.5f;
            float y = ly * (float)GW - 0.5f;
            float xf = floorf(x), yf = floorf(y);
            float tx = x - xf, ty = y - yf;
            int x0 = (int)xf, y0 = (int)yf;
            int x1 = x0 + 1, y1 = y0 + 1;
            bool vx0 = (x0 >= 0), vx1 = (x1 < GW);   // upper side of x0 / lower of x1 always valid
            bool vy0 = (y0 >= 0), vy1 = (y1 < GW);
            float w00 = (1.f - tx) * (1.f - ty);
            float w01 = tx * (1.f - ty);
            float w10 = (1.f - tx) * ty;
            float w11 = tx * ty;
            float a = 0.f;
            if (vx0 && vy0) a = fmaf(w00, fmap[(size_t)(y0 * GW + x0) * Cc], a);
            if (vx1 && vy0) a = fmaf(w01, fmap[(size_t)(y0 * GW + x1) * Cc], a);
            if (vx0 && vy1) a = fmaf(w10, fmap[(size_t)(y1 * GW + x0) * Cc], a);
            if (vx1 && vy1) a = fmaf(w11, fmap[(size_t)(y1 * GW + x1) * Cc], a);
            acc = fmaf(wp[p], a, acc);
        }
        outrow[h * HDd + lane] = acc;
    }
}

// ---------------------------------------------------------------------------
extern "C" void kernel_launch(void* const* d_in, const int* in_sizes, int n_in,
                              void* d_out, int out_size) {
    (void)in_sizes; (void)n_in; (void)out_size;
    const float* q     = (const float*)d_in[0];
    // d_in[1] = k   (unused by reference)
    const float* v     = (const float*)d_in[2];
    const float* Wq    = (const float*)d_in[3];
    const float* bq    = (const float*)d_in[4];
    // d_in[5] = Wk, d_in[6] = bk (unused)
    const float* Wv    = (const float*)d_in[7];
    const float* bv    = (const float*)d_in[8];
    const float* Wo    = (const float*)d_in[9];
    const float* bo    = (const float*)d_in[10];
    const float* Woff  = (const float*)d_in[11];
    const float* boff  = (const float*)d_in[12];
    const float* Wattn = (const float*)d_in[13];
    const float* battn = (const float*)d_in[14];
    float* out = (float*)d_out;

    float *p_vmean, *p_vpm, *p_Woffc, *p_Wattnc, *p_boffc, *p_battnc,
          *p_off, *p_attn, *p_pre;
    cudaGetSymbolAddress((void**)&p_vmean,  g_vmean);
    cudaGetSymbolAddress((void**)&p_vpm,    g_vpm);
    cudaGetSymbolAddress((void**)&p_Woffc,  g_Woffc);
    cudaGetSymbolAddress((void**)&p_Wattnc, g_Wattnc);
    cudaGetSymbolAddress((void**)&p_boffc,  g_boffc);
    cudaGetSymbolAddress((void**)&p_battnc, g_battnc);
    cudaGetSymbolAddress((void**)&p_off,    g_off);
    cudaGetSymbolAddress((void**)&p_attn,   g_attn);
    cudaGetSymbolAddress((void**)&p_pre,    g_pre);

    // 1. vmean = mean over S
    vmean_kernel<<<(Nn * Cc / 4 + 255) / 256, 256>>>(v);

    // 2. folded weights + biases
    biascomb_kernel<<<1, 96>>>(bq, Woff, boff, Wattn, battn);
    sgemm_bias_kernel<128, 64, 16, 8, 4><<<dim3(1, 2), dim3(16, 16)>>>(
        Wq, Woff, nullptr, p_Woffc, 256, 64, 256);
    sgemm_bias_kernel<128, 32, 16, 8, 4><<<dim3(1, 2), dim3(8, 16)>>>(
        Wq, Wattn, nullptr, p_Wattnc, 256, 32, 256);

    // 3. projected mean value map
    sgemm_bias_kernel<128, 64, 16, 8, 4><<<dim3(4, 32), dim3(16, 16)>>>(
        p_vmean, Wv, bv, p_vpm, Nn, Cc, Cc);

    // 4. offsets + attention logits directly from q
    sgemm_bias_kernel<128, 64, 16, 8, 4><<<dim3(1, 256), dim3(16, 16)>>>(
        q, p_Woffc, p_boffc, p_off, ROWS, 64, Cc);
    sgemm_bias_kernel<128, 32, 16, 8, 4><<<dim3(1, 256), dim3(8, 16)>>>(
        q, p_Wattnc, p_battnc, p_attn, ROWS, 32, Cc);

    // 5. softmax + bilinear sampling + point-weighted sum
    sample_kernel<<<ROWS / 8, 256>>>();

    // 6. output projection
    sgemm_bias_kernel<128, 64, 16, 8, 4><<<dim3(4, 256), dim3(16, 16)>>>(
        p_pre, Wo, bo, out, ROWS, Cc, Cc);
}

// round 2
// speedup vs baseline: 1.4998x; 1.4998x over previous
#include <cuda_runtime.h>
#include <cuda_bf16.h>
#include <cstdint>

// ---------------------------------------------------------------------------
// DeformableAttention (B=8, N=4096, C=256, S=4, NH=8, NL=1, NP=4, HD=32)
//
// bf16x3 split-precision tensor-core pipeline:
//   1. vmean    = mean_s v                          (4096 x 256)
//   2. Wfold    = Wq @ [Woff|Wattn] (256x96), bfold = bq@[..] + [boff|battn]
//   3. transpose+split Wv, Wo, Wfold -> bf16 hi/lo [N][K]
//   4. vpm      = vmean @ Wv + bv                   (mma, 4096 x 256)
//   5. offattn  = q @ Wfold + bfold                 (mma, 32768 x 96)
//   6. sampling: softmax + bilinear gather -> pre   (32768 x 256)
//   7. out      = pre @ Wo + bo                     (mma, 32768 x 256)
// ---------------------------------------------------------------------------

namespace {
constexpr int Bn   = 8;
constexpr int Nn   = 4096;
constexpr int Cc   = 256;   // K for all GEMMs
constexpr int NHh  = 8;
constexpr int NPp  = 4;
constexpr int HDd  = 32;
constexpr int ROWS = Bn * Nn;    // 32768
constexpr int GW   = 64;
}

// -------------------- scratch (static device globals) ----------------------
__device__ __align__(16) float g_vmean[Nn * Cc];
__device__ __align__(16) float g_vpm[Nn * Cc];
__device__ __align__(16) float g_Wfold[Cc * 96];
__device__ __align__(16) float g_bfold[96];
__device__ __align__(16) __nv_bfloat16 g_WvT_hi[Cc * Cc];
__device__ __align__(16) __nv_bfloat16 g_WvT_lo[Cc * Cc];
__device__ __align__(16) __nv_bfloat16 g_WoT_hi[Cc * Cc];
__device__ __align__(16) __nv_bfloat16 g_WoT_lo[Cc * Cc];
__device__ __align__(16) __nv_bfloat16 g_WfT_hi[96 * Cc];
__device__ __align__(16) __nv_bfloat16 g_WfT_lo[96 * Cc];
__device__ __align__(16) float g_offattn[(size_t)ROWS * 96];
__device__ __align__(16) float g_pre[(size_t)ROWS * Cc];

// -------------------- mma wrapper ------------------------------------------
__device__ __forceinline__ void mma_bf16(float c[4], const uint32_t a[4],
                                         const uint32_t b[2]) {
    asm volatile(
        "mma.sync.aligned.m16n8k16.row.col.f32.bf16.bf16.f32 "
        "{%0,%1,%2,%3}, {%4,%5,%6,%7}, {%8,%9}, {%0,%1,%2,%3};\n"
        : "+f"(c[0]), "+f"(c[1]), "+f"(c[2]), "+f"(c[3])
        : "r"(a[0]), "r"(a[1]), "r"(a[2]), "r"(a[3]), "r"(b[0]), "r"(b[1]));
}

__device__ __forceinline__ void split_bf16(float x, __nv_bfloat16& h,
                                           __nv_bfloat16& l) {
    h = __float2bfloat16(x);
    l = __float2bfloat16(x - __bfloat162float(h));
}

// -------------------- split-bf16 GEMM: C = A(fp32) @ Bt^T + bias ----------
// A: M x K fp32 (K = 256). Bt: N x K bf16 (hi/lo). C: M x N fp32.
// Block tile 128 x BN, BK = 32. 8 warps (4 x 2), warp tile 32 x (BN/2).
template <int BN>
__global__ void __launch_bounds__(256)
gemm_bf16x3(const float* __restrict__ A,
            const __nv_bfloat16* __restrict__ BtHi,
            const __nv_bfloat16* __restrict__ BtLo,
            const float* __restrict__ bias, float* __restrict__ C,
            int M, int N) {
    constexpr int BM = 128, BK = 32, K = Cc;
    constexpr int LDS_ = BK + 8;           // bf16 elems per smem row (80B)
    constexpr int WN = BN / 2;
    constexpr int NT = WN / 8;
    constexpr int BCH = BN * 4;            // 8-elem chunks in a B tile

    __shared__ __nv_bfloat16 AsH[BM * LDS_];
    __shared__ __nv_bfloat16 AsL[BM * LDS_];
    __shared__ __nv_bfloat16 BsH[BN * LDS_];
    __shared__ __nv_bfloat16 BsL[BN * LDS_];

    const int t = threadIdx.x;
    const int w = t >> 5, l = t & 31;
    const int wm = w & 3, wn = w >> 2;
    const int g = l >> 2, q = l & 3;
    const int blockRow = blockIdx.y * BM;
    const int blockCol = blockIdx.x * BN;

    // A staging: thread t handles row t/2, 16 consecutive K at seg
    const int arow = t >> 1, aseg = (t & 1) * 16;
    // B staging chunks (8 bf16 each)
    constexpr int NCH = (BCH + 255) / 256;

    float acc[2][NT][4];
#pragma unroll
    for (int i = 0; i < 2; i++)
#pragma unroll
        for (int j = 0; j < NT; j++)
#pragma unroll
            for (int x = 0; x < 4; x++) acc[i][j][x] = 0.f;

    float4 af[4];
    uint4 bhv[NCH], blv[NCH];

    // prefetch k0 = 0
    {
        const float* src = A + (size_t)(blockRow + arow) * K + aseg;
#pragma unroll
        for (int i = 0; i < 4; i++) af[i] = *(const float4*)(src + i * 4);
#pragma unroll
        for (int c = 0; c < NCH; c++) {
            int ch = t + c * 256;
            if (ch < BCH) {
                int brow = ch >> 2, bseg = (ch & 3) * 8;
                bhv[c] = *(const uint4*)(BtHi + (size_t)(blockCol + brow) * K + bseg);
                blv[c] = *(const uint4*)(BtLo + (size_t)(blockCol + brow) * K + bseg);
            }
        }
    }

    for (int k0 = 0; k0 < K; k0 += BK) {
        // store staged tile to smem
        {
            const float* fx = (const float*)af;
            __nv_bfloat16 hbuf[16], lbuf[16];
#pragma unroll
            for (int i = 0; i < 16; i++) split_bf16(fx[i], hbuf[i], lbuf[i]);
            *(uint4*)&AsH[arow * LDS_ + aseg]     = *(const uint4*)&hbuf[0];
            *(uint4*)&AsH[arow * LDS_ + aseg + 8] = *(const uint4*)&hbuf[8];
            *(uint4*)&AsL[arow * LDS_ + aseg]     = *(const uint4*)&lbuf[0];
            *(uint4*)&AsL[arow * LDS_ + aseg + 8] = *(const uint4*)&lbuf[8];
#pragma unroll
            for (int c = 0; c < NCH; c++) {
                int ch = t + c * 256;
                if (ch < BCH) {
                    int brow = ch >> 2, bseg = (ch & 3) * 8;
                    *(uint4*)&BsH[brow * LDS_ + bseg] = bhv[c];
                    *(uint4*)&BsL[brow * LDS_ + bseg] = blv[c];
                }
            }
        }
        __syncthreads();

        // prefetch next tile
        if (k0 + BK < K) {
            const float* src = A + (size_t)(blockRow + arow) * K + k0 + BK + aseg;
#pragma unroll
            for (int i = 0; i < 4; i++) af[i] = *(const float4*)(src + i * 4);
#pragma unroll
            for (int c = 0; c < NCH; c++) {
                int ch = t + c * 256;
                if (ch < BCH) {
                    int brow = ch >> 2, bseg = (ch & 3) * 8;
                    bhv[c] = *(const uint4*)(BtHi + (size_t)(blockCol + brow) * K + k0 + BK + bseg);
                    blv[c] = *(const uint4*)(BtLo + (size_t)(blockCol + brow) * K + k0 + BK + bseg);
                }
            }
        }

        // compute on current smem tile
#pragma unroll
        for (int ks = 0; ks < 2; ks++) {
            const int kb = ks * 16;
            uint32_t aH[2][4], aL[2][4];
#pragma unroll
            for (int mt = 0; mt < 2; mt++) {
                int m0 = wm * 32 + mt * 16;
                aH[mt][0] = *(const uint32_t*)&AsH[(m0 + g) * LDS_ + kb + 2 * q];
                aH[mt][1] = *(const uint32_t*)&AsH[(m0 + g + 8) * LDS_ + kb + 2 * q];
                aH[mt][2] = *(const uint32_t*)&AsH[(m0 + g) * LDS_ + kb + 2 * q + 8];
                aH[mt][3] = *(const uint32_t*)&AsH[(m0 + g + 8) * LDS_ + kb + 2 * q + 8];
                aL[mt][0] = *(const uint32_t*)&AsL[(m0 + g) * LDS_ + kb + 2 * q];
                aL[mt][1] = *(const uint32_t*)&AsL[(m0 + g + 8) * LDS_ + kb + 2 * q];
                aL[mt][2] = *(const uint32_t*)&AsL[(m0 + g) * LDS_ + kb + 2 * q + 8];
                aL[mt][3] = *(const uint32_t*)&AsL[(m0 + g + 8) * LDS_ + kb + 2 * q + 8];
            }
            uint32_t bH[NT][2], bL[NT][2];
#pragma unroll
            for (int nt = 0; nt < NT; nt++) {
                int n0 = wn * WN + nt * 8 + g;
                bH[nt][0] = *(const uint32_t*)&BsH[n0 * LDS_ + kb + 2 * q];
                bH[nt][1] = *(const uint32_t*)&BsH[n0 * LDS_ + kb + 2 * q + 8];
                bL[nt][0] = *(const uint32_t*)&BsL[n0 * LDS_ + kb + 2 * q];
                bL[nt][1] = *(const uint32_t*)&BsL[n0 * LDS_ + kb + 2 * q + 8];
            }
#pragma unroll
            for (int mt = 0; mt < 2; mt++)
#pragma unroll
                for (int nt = 0; nt < NT; nt++) {
                    mma_bf16(acc[mt][nt], aH[mt], bH[nt]);
                    mma_bf16(acc[mt][nt], aH[mt], bL[nt]);
                    mma_bf16(acc[mt][nt], aL[mt], bH[nt]);
                }
        }
        __syncthreads();
    }

    // epilogue
#pragma unroll
    for (int mt = 0; mt < 2; mt++) {
        int row = blockRow + wm * 32 + mt * 16 + g;
#pragma unroll
        for (int nt = 0; nt < NT; nt++) {
            int col = blockCol + wn * WN + nt * 8 + 2 * q;
            float2 bb = make_float2(0.f, 0.f);
            if (bias) bb = *(const float2*)&bias[col];
            float2 o0 = make_float2(acc[mt][nt][0] + bb.x, acc[mt][nt][1] + bb.y);
            float2 o1 = make_float2(acc[mt][nt][2] + bb.x, acc[mt][nt][3] + bb.y);
            *(float2*)&C[(size_t)row * N + col] = o0;
            *(float2*)&C[(size_t)(row + 8) * N + col] = o1;
        }
    }
}

// -------------------- mean over S=4 ----------------------------------------
__global__ void vmean_kernel(const float* __restrict__ v) {
    const int tot = Nn * Cc / 4;
    int i = blockIdx.x * blockDim.x + threadIdx.x;
    if (i < tot) {
        const float4* v4 = reinterpret_cast<const float4*>(v);
        float4 a = v4[i], b = v4[i + tot], c = v4[i + 2 * tot], d = v4[i + 3 * tot];
        float4 r;
        r.x = 0.25f * (a.x + b.x + c.x + d.x);
        r.y = 0.25f * (a.y + b.y + c.y + d.y);
        r.z = 0.25f * (a.z + b.z + c.z + d.z);
        r.w = 0.25f * (a.w + b.w + c.w + d.w);
        reinterpret_cast<float4*>(g_vmean)[i] = r;
    }
}

// -------------------- weight fold: Wfold[k][c] = sum_j Wq[k][j]*Wcat[j][c] -
__global__ void fold_kernel(const float* __restrict__ Wq,
                            const float* __restrict__ Woff,
                            const float* __restrict__ Wattn) {
    int idx = blockIdx.x * blockDim.x + threadIdx.x;   // 256*96 threads
    if (idx >= Cc * 96) return;
    int k = idx / 96, c = idx % 96;
    const float* wq = Wq + k * Cc;
    float s = 0.f;
    if (c < 64) {
#pragma unroll 8
        for (int j = 0; j < Cc; j++) s = fmaf(wq[j], Woff[j * 64 + c], s);
    } else {
        int cc2 = c - 64;
#pragma unroll 8
        for (int j = 0; j < Cc; j++) s = fmaf(wq[j], Wattn[j * 32 + cc2], s);
    }
    g_Wfold[k * 96 + c] = s;
}

__global__ void biascomb_kernel(const float* __restrict__ bq,
                                const float* __restrict__ Woff,
                                const float* __restrict__ boff,
                                const float* __restrict__ Wattn,
                                const float* __restrict__ battn) {
    int j = threadIdx.x;
    if (j < 64) {
        float s = boff[j];
        for (int k = 0; k < Cc; k++) s += bq[k] * Woff[k * 64 + j];
        g_bfold[j] = s;
    } else if (j < 96) {
        int jj = j - 64;
        float s = battn[jj];
        for (int k = 0; k < Cc; k++) s += bq[k] * Wattn[k * 32 + jj];
        g_bfold[j] = s;
    }
}

// -------------------- transpose + split B matrices -------------------------
__global__ void convertT_kernel(const float* __restrict__ Wv,
                                const float* __restrict__ Wo) {
    int idx = blockIdx.x * blockDim.x + threadIdx.x;
    const int S1 = Cc * Cc, S2 = 2 * Cc * Cc, S3 = 2 * Cc * Cc + 96 * Cc;
    if (idx < S1) {
        int n = idx / Cc, k = idx % Cc;            // out [n][k], in [k][n]
        split_bf16(Wv[k * Cc + n], g_WvT_hi[idx], g_WvT_lo[idx]);
    } else if (idx < S2) {
        int li = idx - S1;
        int n = li / Cc, k = li % Cc;
        split_bf16(Wo[k * Cc + n], g_WoT_hi[li], g_WoT_lo[li]);
    } else if (idx < S3) {
        int li = idx - S2;
        int n = li / Cc, k = li % Cc;              // n in 0..95
        split_bf16(g_Wfold[k * 96 + n], g_WfT_hi[li], g_WfT_lo[li]);
    }
}

// -------------------- sampling ---------------------------------------------
__global__ void __launch_bounds__(256) sample_kernel() {
    __shared__ float s_off[8][64];
    __shared__ float s_attn[8][32];
    const int w    = threadIdx.x >> 5;
    const int lane = threadIdx.x & 31;
    const int row  = blockIdx.x * 8 + w;

    const float* oarow = g_offattn + (size_t)row * 96;
    s_off[w][lane]      = oarow[lane];
    s_off[w][lane + 32] = oarow[lane + 32];
    s_attn[w][lane]     = oarow[64 + lane];
    __syncwarp();

    const int n = row & (Nn - 1);
    const float refx = (float)(n & (GW - 1)) * (1.0f / 63.0f);
    const float refy = (float)(n >> 6) * (1.0f / 63.0f);
    float* outrow = g_pre + (size_t)row * Cc;

#pragma unroll
    for (int h = 0; h < NHh; h++) {
        float l0 = s_attn[w][h * 4 + 0];
        float l1 = s_attn[w][h * 4 + 1];
        float l2 = s_attn[w][h * 4 + 2];
        float l3 = s_attn[w][h * 4 + 3];
        float m  = fmaxf(fmaxf(l0, l1), fmaxf(l2, l3));
        float e0 = __expf(l0 - m), e1 = __expf(l1 - m);
        float e2 = __expf(l2 - m), e3 = __expf(l3 - m);
        float inv = 1.0f / (e0 + e1 + e2 + e3);
        float wp[4] = {e0 * inv, e1 * inv, e2 * inv, e3 * inv};

        const float* fmap = g_vpm + h * HDd + lane;
        float acc = 0.f;
#pragma unroll
        for (int p = 0; p < NPp; p++) {
            float ox = s_off[w][h * 8 + p * 2 + 0];
            float oy = s_off[w][h * 8 + p * 2 + 1];
            float lx = fminf(fmaxf(refx + ox, 0.f), 1.f);
            float ly = fminf(fmaxf(refy + oy, 0.f), 1.f);
            float x = lx * (float)GW - 0.5f;
            float y = ly * (float)GW - 0.5f;
            float xf = floorf(x), yf = floorf(y);
            float tx = x - xf, ty = y - yf;
            int x0 = (int)xf, y0 = (int)yf;
            int x1 = x0 + 1, y1 = y0 + 1;
            bool vx0 = (x0 >= 0), vx1 = (x1 < GW);
            bool vy0 = (y0 >= 0), vy1 = (y1 < GW);
            float w00 = (1.f - tx) * (1.f - ty);
            float w01 = tx * (1.f - ty);
            float w10 = (1.f - tx) * ty;
            float w11 = tx * ty;
            float a = 0.f;
            if (vx0 && vy0) a = fmaf(w00, fmap[(size_t)(y0 * GW + x0) * Cc], a);
            if (vx1 && vy0) a = fmaf(w01, fmap[(size_t)(y0 * GW + x1) * Cc], a);
            if (vx0 && vy1) a = fmaf(w10, fmap[(size_t)(y1 * GW + x0) * Cc], a);
            if (vx1 && vy1) a = fmaf(w11, fmap[(size_t)(y1 * GW + x1) * Cc], a);
            acc = fmaf(wp[p], a, acc);
        }
        outrow[h * HDd + lane] = acc;
    }
}

// ---------------------------------------------------------------------------
extern "C" void kernel_launch(void* const* d_in, const int* in_sizes, int n_in,
                              void* d_out, int out_size) {
    (void)in_sizes; (void)n_in; (void)out_size;
    const float* q     = (const float*)d_in[0];
    const float* v     = (const float*)d_in[2];
    const float* Wq    = (const float*)d_in[3];
    const float* bq    = (const float*)d_in[4];
    const float* Wv    = (const float*)d_in[7];
    const float* bv    = (const float*)d_in[8];
    const float* Wo    = (const float*)d_in[9];
    const float* bo    = (const float*)d_in[10];
    const float* Woff  = (const float*)d_in[11];
    const float* boff  = (const float*)d_in[12];
    const float* Wattn = (const float*)d_in[13];
    const float* battn = (const float*)d_in[14];
    float* out = (float*)d_out;

    float *p_vmean, *p_vpm, *p_bfold, *p_offattn, *p_pre;
    __nv_bfloat16 *p_WvH, *p_WvL, *p_WoH, *p_WoL, *p_WfH, *p_WfL;
    cudaGetSymbolAddress((void**)&p_vmean,   g_vmean);
    cudaGetSymbolAddress((void**)&p_vpm,     g_vpm);
    cudaGetSymbolAddress((void**)&p_bfold,   g_bfold);
    cudaGetSymbolAddress((void**)&p_offattn, g_offattn);
    cudaGetSymbolAddress((void**)&p_pre,     g_pre);
    cudaGetSymbolAddress((void**)&p_WvH,     g_WvT_hi);
    cudaGetSymbolAddress((void**)&p_WvL,     g_WvT_lo);
    cudaGetSymbolAddress((void**)&p_WoH,     g_WoT_hi);
    cudaGetSymbolAddress((void**)&p_WoL,     g_WoT_lo);
    cudaGetSymbolAddress((void**)&p_WfH,     g_WfT_hi);
    cudaGetSymbolAddress((void**)&p_WfL,     g_WfT_lo);

    // 1. mean over S
    vmean_kernel<<<(Nn * Cc / 4 + 255) / 256, 256>>>(v);

    // 2. folded weights + bias
    fold_kernel<<<(Cc * 96 + 255) / 256, 256>>>(Wq, Woff, Wattn);
    biascomb_kernel<<<1, 96>>>(bq, Woff, boff, Wattn, battn);

    // 3. transpose + split all B matrices (Wfold must exist first)
    {
        int tot = 2 * Cc * Cc + 96 * Cc;
        convertT_kernel<<<(tot + 255) / 256, 256>>>(Wv, Wo);
    }

    // 4. vpm = vmean @ Wv + bv
    gemm_bf16x3<64><<<dim3(Cc / 64, Nn / 128), 256>>>(
        p_vmean, p_WvH, p_WvL, bv, p_vpm, Nn, Cc);

    // 5. offattn = q @ Wfold + bfold
    gemm_bf16x3<96><<<dim3(1, ROWS / 128), 256>>>(
        q, p_WfH, p_WfL, p_bfold, p_offattn, ROWS, 96);

    // 6. sampling
    sample_kernel<<<ROWS / 8, 256>>>();

    // 7. out = pre @ Wo + bo
    gemm_bf16x3<64><<<dim3(Cc / 64, ROWS / 128), 256>>>(
        p_pre, p_WoH, p_WoL, bo, out, ROWS, Cc);
}